// round 7
// baseline (speedup 1.0000x reference)
#include <cuda_runtime.h>
#include <cuda.h>
#include <math.h>
#include <stdint.h>

// Problem constants
#define BB    8
#define CC    128
#define NN    65536
#define NOBJ  64

#define PBLK     512               // points per stage-1 block (chunk)
#define HT       32                // points per TMA tile (SW128 box: 32x128)
#define NHT      (PBLK / HT)       // 16 tiles
#define THREADS1 512               // 16 warps; warp w owns segs 4w..4w+3
#define NWARP    16
#define NCHUNK   (NN / PBLK)       // 128
#define NCID     (BB * NCHUNK)     // 1024 chunks total
#define NBUCK    (NWARP * NHT)     // 256 buckets per chunk
#define TILE_B   (HT * CC * 4)     // 16384 bytes per tile

// Scratch (static device arrays: allowed). __align__(16) for vector casts.
__device__ float g_partial[(size_t)NCID * NOBJ * CC];                  // 32 MB
__device__ __align__(16) unsigned short g_entries[NCID * PBLK];        // 1 MB
__device__ __align__(16) unsigned short g_pref[NCID * (NBUCK + 1)];    // 514 KB

// ---------------------------------------------------------------------------
// Prep: dtype-probe box_idx (int32 vs int64), then counting-sort each chunk's
// 512 points into 256 buckets keyed (owner_warp = s>>2, tile = pt>>5).
// Entry = pt | (s&3)<<9. Bucket contents deterministic; intra-bucket order
// varies but max() erases it.
// ---------------------------------------------------------------------------
__global__ void prep_sort(const int* __restrict__ idx32) {
    __shared__ int ok;
    __shared__ int hist[NBUCK];
    __shared__ int wsum[8];
    __shared__ int pos[NBUCK];

    const int tid = threadIdx.x;          // 256
    const int cid = blockIdx.x;           // 1024 chunks
    if (tid == 0) ok = 1;
    hist[tid] = 0;
    __syncthreads();
    {   // int64 in [0,64) -> int32 view [v,0,v,0,...]; random int32 can't
        // keep all 256 odd words zero -> unambiguous.
        int lo = idx32[2 * tid];
        int hi = idx32[2 * tid + 1];
        if (hi != 0 || lo < 0 || lo >= NOBJ) atomicAnd(&ok, 0);
    }
    __syncthreads();
    const int stride = ok ? 2 : 1;

    const int p0 = tid, p1 = tid + 256;   // two points per thread
    int s0 = idx32[(size_t)(cid * PBLK + p0) * stride];
    int s1 = idx32[(size_t)(cid * PBLK + p1) * stride];
    int b0 = (s0 >> 2) * NHT + (p0 >> 5);
    int b1 = (s1 >> 2) * NHT + (p1 >> 5);
    atomicAdd(&hist[b0], 1);
    atomicAdd(&hist[b1], 1);
    __syncthreads();

    // exclusive scan over hist[256]
    const int lane = tid & 31, wid = tid >> 5;
    int v = hist[tid];
    int inc = v;
    #pragma unroll
    for (int d = 1; d < 32; d <<= 1) {
        int t = __shfl_up_sync(0xffffffffu, inc, d);
        if (lane >= d) inc += t;
    }
    if (lane == 31) wsum[wid] = inc;
    __syncthreads();
    if (tid == 0) {
        int run = 0;
        #pragma unroll
        for (int i = 0; i < 8; ++i) { int t = wsum[i]; wsum[i] = run; run += t; }
    }
    __syncthreads();
    int exc = inc - v + wsum[wid];
    pos[tid] = exc;
    g_pref[cid * (NBUCK + 1) + tid] = (unsigned short)exc;
    if (tid == 0) g_pref[cid * (NBUCK + 1) + NBUCK] = (unsigned short)PBLK;
    __syncthreads();

    int r0 = atomicAdd(&pos[b0], 1);
    g_entries[cid * PBLK + r0] = (unsigned short)(p0 | ((s0 & 3) << 9));
    int r1 = atomicAdd(&pos[b1], 1);
    g_entries[cid * PBLK + r1] = (unsigned short)(p1 | ((s1 & 3) << 9));
}

// ---- mbarrier helpers -------------------------------------------------------
__device__ __forceinline__ void mbar_init(uint32_t a, uint32_t cnt) {
    asm volatile("mbarrier.init.shared.b64 [%0], %1;" :: "r"(a), "r"(cnt) : "memory");
}
__device__ __forceinline__ void mbar_expect_tx(uint32_t a, uint32_t bytes) {
    asm volatile("mbarrier.arrive.expect_tx.shared.b64 _, [%0], %1;"
                 :: "r"(a), "r"(bytes) : "memory");
}
__device__ __forceinline__ void mbar_wait(uint32_t a, uint32_t parity) {
    asm volatile(
        "{\n\t.reg .pred P;\n\t"
        "W: mbarrier.try_wait.parity.acquire.cta.shared::cta.b64 P, [%0], %1, 0x989680;\n\t"
        "@P bra D;\n\t"
        "bra W;\n\t"
        "D:\n\t}"
        :: "r"(a), "r"(parity) : "memory");
}
__device__ __forceinline__ void tma_load_2d(uint32_t dst, const CUtensorMap* tm,
                                            int x, int y, uint32_t mbar) {
    asm volatile(
        "cp.async.bulk.tensor.2d.shared::cta.global.tile.mbarrier::complete_tx::bytes "
        "[%0], [%1, {%2, %3}], [%4];"
        :: "r"(dst), "l"(tm), "r"(x), "r"(y), "r"(mbar) : "memory");
}

// ---------------------------------------------------------------------------
// Stage 1: TMA-fed register-accumulator segment max.
//   Loads: one UTMALDG per 16KB tile (box {32 pts, 128 ch}, SW128), elected
//   thread, mbarrier complete_tx, double-buffered. Removes the 16K-LDGSTS
//   per-block instruction storm that bound Rounds 4/6.
//   Compute: warp w owns segs 4w..4w+3; lane l owns channels {l,l+32,l+64,l+96};
//   16 register accumulators, predicated FMAX. SW128 gather:
//   addr(c,pt) = c*128B + (((pt>>2)^(c&7))<<4) + (pt&3)*4.
// ---------------------------------------------------------------------------
__global__ __launch_bounds__(THREADS1) void seg_max_stage1(
    const __grid_constant__ CUtensorMap tmap)
{
    __shared__ __align__(1024) float buf[2][HT * CC];  // 2 x 16 KB
    __shared__ __align__(8) unsigned long long mbar[2];
    __shared__ unsigned short Psm[NBUCK + 2];
    __shared__ unsigned short Esm[PBLK];

    const int tid  = threadIdx.x;
    const int lane = tid & 31;
    const int w    = tid >> 5;
    const int cid  = blockIdx.x;
    const int y0   = (cid >> 7) * CC;          // batch row base
    const int x0   = (cid & 127) * PBLK;       // point base

    const uint32_t mb0  = (uint32_t)__cvta_generic_to_shared(&mbar[0]);
    const uint32_t mb1  = (uint32_t)__cvta_generic_to_shared(&mbar[1]);
    const uint32_t b0u  = (uint32_t)__cvta_generic_to_shared(&buf[0][0]);
    const uint32_t b1u  = (uint32_t)__cvta_generic_to_shared(&buf[1][0]);

    if (tid < NBUCK + 1) Psm[tid] = g_pref[cid * (NBUCK + 1) + tid];
    if (tid < PBLK / 2)
        ((uint32_t*)Esm)[tid] = ((const uint32_t*)(g_entries + cid * PBLK))[tid];

    if (tid == 0) {
        mbar_init(mb0, 1);
        mbar_init(mb1, 1);
        asm volatile("fence.proxy.async.shared::cta;" ::: "memory");
    }
    __syncthreads();

    if (tid == 0) {
        mbar_expect_tx(mb0, TILE_B);
        tma_load_2d(b0u, &tmap, x0, y0, mb0);
        mbar_expect_tx(mb1, TILE_B);
        tma_load_2d(b1u, &tmap, x0 + HT, y0, mb1);
    }

    float r0[4], r1[4], r2[4], r3[4];
    #pragma unroll
    for (int k = 0; k < 4; ++k) {
        r0[k] = -INFINITY; r1[k] = -INFINITY;
        r2[k] = -INFINITY; r3[k] = -INFINITY;
    }

    for (int ht = 0; ht < NHT; ++ht) {
        const uint32_t mb = (ht & 1) ? mb1 : mb0;
        mbar_wait(mb, (ht >> 1) & 1);

        const float* tb = buf[ht & 1];
        const int i0 = Psm[w * NHT + ht];
        const int i1 = Psm[w * NHT + ht + 1];
        for (int i = i0; i < i1; ++i) {           // warp-uniform walk
            const unsigned e  = Esm[i];           // broadcast
            const int lp = e & 31;                // local point in tile
            const int sl = (e >> 9) & 3;          // warp-uniform 0..3
            const int sw = (((lp >> 2) ^ (lane & 7)) << 2) + (lp & 3);
            float v0 = tb[(lane     ) * HT + sw];
            float v1 = tb[(lane + 32) * HT + sw];
            float v2 = tb[(lane + 64) * HT + sw];
            float v3 = tb[(lane + 96) * HT + sw];
            r0[0] = (sl == 0) ? fmaxf(r0[0], v0) : r0[0];
            r0[1] = (sl == 0) ? fmaxf(r0[1], v1) : r0[1];
            r0[2] = (sl == 0) ? fmaxf(r0[2], v2) : r0[2];
            r0[3] = (sl == 0) ? fmaxf(r0[3], v3) : r0[3];
            r1[0] = (sl == 1) ? fmaxf(r1[0], v0) : r1[0];
            r1[1] = (sl == 1) ? fmaxf(r1[1], v1) : r1[1];
            r1[2] = (sl == 1) ? fmaxf(r1[2], v2) : r1[2];
            r1[3] = (sl == 1) ? fmaxf(r1[3], v3) : r1[3];
            r2[0] = (sl == 2) ? fmaxf(r2[0], v0) : r2[0];
            r2[1] = (sl == 2) ? fmaxf(r2[1], v1) : r2[1];
            r2[2] = (sl == 2) ? fmaxf(r2[2], v2) : r2[2];
            r2[3] = (sl == 2) ? fmaxf(r2[3], v3) : r2[3];
            r3[0] = (sl == 3) ? fmaxf(r3[0], v0) : r3[0];
            r3[1] = (sl == 3) ? fmaxf(r3[1], v1) : r3[1];
            r3[2] = (sl == 3) ? fmaxf(r3[2], v2) : r3[2];
            r3[3] = (sl == 3) ? fmaxf(r3[3], v3) : r3[3];
        }
        __syncthreads();                          // buffer fully consumed
        if (tid == 0 && ht + 2 < NHT) {
            mbar_expect_tx(mb, TILE_B);
            tma_load_2d((ht & 1) ? b1u : b0u, &tmap, x0 + (ht + 2) * HT, y0, mb);
        }
    }

    // Writeout: 128B-coalesced per (seg, k-group) row segment.
    float* outp = g_partial + (size_t)cid * (NOBJ * CC) + (4 * w) * CC + lane;
    #pragma unroll
    for (int k = 0; k < 4; ++k) {
        outp[0 * CC + 32 * k] = r0[k];
        outp[1 * CC + 32 * k] = r1[k];
        outp[2 * CC + 32 * k] = r2[k];
        outp[3 * CC + 32 * k] = r3[k];
    }
}

// ---------------------------------------------------------------------------
// Stage 2: reduce 128 per-chunk partials per (b, seg, c-quad); -inf -> 0.
// ---------------------------------------------------------------------------
__global__ void seg_max_stage2(float* __restrict__ out) {
    int o4 = blockIdx.x * blockDim.x + threadIdx.x;   // 0..16383 float4s
    int c4 = o4 & (CC / 4 - 1);
    int g  = o4 >> 5;
    int b  = g >> 6;
    int s  = g & (NOBJ - 1);

    const float4* __restrict__ p =
        (const float4*)(g_partial + (size_t)b * NCHUNK * (NOBJ * CC) + s * CC) + c4;

    float4 m = make_float4(-INFINITY, -INFINITY, -INFINITY, -INFINITY);
    #pragma unroll 4
    for (int k = 0; k < NCHUNK; ++k) {
        float4 v = p[(size_t)k * (NOBJ * CC / 4)];
        m.x = fmaxf(m.x, v.x); m.y = fmaxf(m.y, v.y);
        m.z = fmaxf(m.z, v.z); m.w = fmaxf(m.w, v.w);
    }
    float4 r;
    r.x = isfinite(m.x) ? m.x : 0.0f;
    r.y = isfinite(m.y) ? m.y : 0.0f;
    r.z = isfinite(m.z) ? m.z : 0.0f;
    r.w = isfinite(m.w) ? m.w : 0.0f;
    ((float4*)out)[o4] = r;
}

// ---------------------------------------------------------------------------
typedef CUresult (*EncodeFn)(
    CUtensorMap*, CUtensorMapDataType, cuuint32_t, void*,
    const cuuint64_t*, const cuuint64_t*, const cuuint32_t*, const cuuint32_t*,
    CUtensorMapInterleave, CUtensorMapSwizzle, CUtensorMapL2promotion,
    CUtensorMapFloatOOBfill);

extern "C" void kernel_launch(void* const* d_in, const int* in_sizes, int n_in,
                              void* d_out, int out_size)
{
    const float* feat = nullptr;
    const int*   idx  = nullptr;
    for (int i = 0; i < n_in; ++i) {
        if (in_sizes[i] == BB * CC * NN)  feat = (const float*)d_in[i];
        else if (in_sizes[i] == BB * NN)  idx  = (const int*)d_in[i];
    }

    // Tensormap encoder via runtime driver-entry hook (no -lcuda needed).
    static EncodeFn enc = nullptr;
    if (!enc) {
        void* fp = nullptr;
        cudaDriverEntryPointQueryResult qr;
#if CUDART_VERSION >= 12050
        cudaGetDriverEntryPointByVersion("cuTensorMapEncodeTiled", &fp, 12000,
                                         cudaEnableDefault, &qr);
#else
        cudaGetDriverEntryPoint("cuTensorMapEncodeTiled", &fp,
                                cudaEnableDefault, &qr);
#endif
        enc = (EncodeFn)fp;
    }

    CUtensorMap tmap;
    {
        cuuint64_t dims[2]    = {(cuuint64_t)NN, (cuuint64_t)(BB * CC)};
        cuuint64_t strides[1] = {(cuuint64_t)NN * 4};
        cuuint32_t box[2]     = {HT, CC};       // 32 pts x 128 ch = 16 KB
        cuuint32_t estr[2]    = {1, 1};
        enc(&tmap, CU_TENSOR_MAP_DATA_TYPE_FLOAT32, 2, (void*)feat,
            dims, strides, box, estr,
            CU_TENSOR_MAP_INTERLEAVE_NONE, CU_TENSOR_MAP_SWIZZLE_128B,
            CU_TENSOR_MAP_L2_PROMOTION_L2_128B,
            CU_TENSOR_MAP_FLOAT_OOB_FILL_NONE);
    }

    prep_sort<<<NCID, 256>>>(idx);
    seg_max_stage1<<<NCID, THREADS1>>>(tmap);
    seg_max_stage2<<<(BB * NOBJ * CC / 4) / 256, 256>>>((float*)d_out);
}